// round 8
// baseline (speedup 1.0000x reference)
#include <cuda_runtime.h>
#include <cuda_bf16.h>
#include <math.h>
#include <stdint.h>

// ---------------- problem constants ----------------
#define Bz    4
#define Hh    128
#define Wfull 256
#define Cc    192
#define Ll    (Hh*Wfull)
#define HEADS 6
#define HD    32
#define NWIN  512
#define BW    (Bz*NWIN)         // 2048 windows
#define MTOK  (BW*64)           // 131072 window tokens
#define HID   768

typedef __nv_bfloat16 bf16;

// ---------------- scratch ----------------
__device__ bf16  g_q  [MTOK*Cc];
__device__ bf16  g_kv [MTOK*2*Cc];
__device__ bf16  g_ao [MTOK*Cc];
__device__ bf16  g_h  [MTOK*HID];
// bf16 weights
__device__ bf16  g_qwb [Cc*Cc];
__device__ bf16  g_kvwb[Cc*2*Cc];
__device__ bf16  g_pwb [Cc*Cc];
__device__ bf16  g_f1wb[Cc*HID];
__device__ bf16  g_f2wb[HID*Cc];

__device__ __forceinline__ int map_row(int t) {
    int b_  = t >> 6;
    int n   = t & 63;
    int b   = b_ >> 9;
    int win = b_ & 511;
    int hi  = win >> 5;
    int wi  = win & 31;
    int r   = n >> 3, c = n & 7;
    int sh  = (hi * 8 + r + 4) & (Hh - 1);
    int sw  = (wi * 8 + c + 4) & (Wfull - 1);
    return b * Ll + sh * Wfull + sw;
}

__device__ __forceinline__ uint32_t smem_u32(const void* p) {
    return (uint32_t)__cvta_generic_to_shared(p);
}
__device__ __forceinline__ uint32_t packbf(float x, float y) {
    __nv_bfloat162 t = __floats2bfloat162_rn(x, y);
    return *reinterpret_cast<uint32_t*>(&t);
}
__device__ __forceinline__ void ldsm_x4(uint32_t& r0, uint32_t& r1, uint32_t& r2, uint32_t& r3, uint32_t a) {
    asm volatile("ldmatrix.sync.aligned.m8n8.x4.shared.b16 {%0,%1,%2,%3}, [%4];"
                 : "=r"(r0), "=r"(r1), "=r"(r2), "=r"(r3) : "r"(a));
}
__device__ __forceinline__ void ldsm_x4t(uint32_t& r0, uint32_t& r1, uint32_t& r2, uint32_t& r3, uint32_t a) {
    asm volatile("ldmatrix.sync.aligned.m8n8.x4.trans.shared.b16 {%0,%1,%2,%3}, [%4];"
                 : "=r"(r0), "=r"(r1), "=r"(r2), "=r"(r3) : "r"(a));
}
#define MMA_BF16(C, A0,A1,A2,A3, B0,B1) \
    asm volatile("mma.sync.aligned.m16n8k16.row.col.f32.bf16.bf16.f32 " \
        "{%0,%1,%2,%3},{%4,%5,%6,%7},{%8,%9},{%0,%1,%2,%3};" \
        : "+f"(C[0]), "+f"(C[1]), "+f"(C[2]), "+f"(C[3]) \
        : "r"(A0), "r"(A1), "r"(A2), "r"(A3), "r"(B0), "r"(B1))

// ---------------- all weights fp32 -> bf16, one launch ----------------
#define W1 (Cc*Cc)
#define W2 (W1 + Cc*2*Cc)
#define W3 (W2 + Cc*Cc)
#define W4 (W3 + Cc*HID)
#define W5 (W4 + HID*Cc)
__global__ void cvt_all_kernel(const float* __restrict__ qw, const float* __restrict__ kvw,
                               const float* __restrict__ pw, const float* __restrict__ f1w,
                               const float* __restrict__ f2w) {
    int i = blockIdx.x * 256 + threadIdx.x;
    if (i < W1)      g_qwb [i]      = __float2bfloat16_rn(qw [i]);
    else if (i < W2) g_kvwb[i - W1] = __float2bfloat16_rn(kvw[i - W1]);
    else if (i < W3) g_pwb [i - W2] = __float2bfloat16_rn(pw [i - W2]);
    else if (i < W4) g_f1wb[i - W3] = __float2bfloat16_rn(f1w[i - W3]);
    else if (i < W5) g_f2wb[i - W4] = __float2bfloat16_rn(f2w[i - W4]);
}

// ---------------- attention: bf16 mma, analytic mask --------------
__device__ __forceinline__ int rel_idx(int n, int m) {
    return ((n >> 3) - (m >> 3) + 7) * 15 + ((n & 7) - (m & 7) + 7);
}

__global__ __launch_bounds__(128) void attn_kernel(const float* __restrict__ rpb_table)
{
    __shared__ bf16  qs[64][40];
    __shared__ bf16  ks[64][40];
    __shared__ bf16  vs[64][40];
    __shared__ float rpb_s[225];

    int bx   = blockIdx.x;
    int h    = bx % HEADS;
    int w    = bx / HEADS;
    int tid  = threadIdx.x;
    int lane = tid & 31;
    int warp = tid >> 5;
    int base = w * 64;

    int fH = (((w >> 5) & 15) == 15) ? 1 : 0;
    int fW = ((w & 31) == 31) ? 1 : 0;

#pragma unroll
    for (int i = 0; i < 2; i++) {
        int c   = tid + i * 128;
        int row = c >> 2;
        int off = (c & 3) * 8;
        const bf16* gq = g_q  + (size_t)(base + row) * Cc  + h * HD + off;
        const bf16* gk = g_kv + (size_t)(base + row) * 384 + h * HD + off;
        const bf16* gv = g_kv + (size_t)(base + row) * 384 + 192 + h * HD + off;
        asm volatile("cp.async.ca.shared.global [%0], [%1], 16;" :: "r"(smem_u32(&qs[row][off])), "l"(gq));
        asm volatile("cp.async.ca.shared.global [%0], [%1], 16;" :: "r"(smem_u32(&ks[row][off])), "l"(gk));
        asm volatile("cp.async.ca.shared.global [%0], [%1], 16;" :: "r"(smem_u32(&vs[row][off])), "l"(gv));
    }
    asm volatile("cp.async.commit_group;");
    for (int i = tid; i < 225; i += 128)
        rpb_s[i] = __ldg(rpb_table + i * HEADS + h);
    asm volatile("cp.async.wait_group 0;");
    __syncthreads();

    int r  = lane >> 2;
    int q  = lane & 3;
    int n0 = warp * 16;

    float Sc[8][4];
#pragma unroll
    for (int nt = 0; nt < 8; nt++)
#pragma unroll
        for (int e = 0; e < 4; e++) Sc[nt][e] = 0.f;

#pragma unroll
    for (int kc = 0; kc < 2; kc++) {
        uint32_t a0, a1, a2, a3;
        ldsm_x4(a0, a1, a2, a3, smem_u32(&qs[n0 + (lane & 15)][kc * 16 + (lane >> 4) * 8]));
#pragma unroll
        for (int p = 0; p < 4; p++) {
            uint32_t r0, r1, r2, r3;
            ldsm_x4(r0, r1, r2, r3, smem_u32(&ks[p * 16 + (lane & 15)][kc * 16 + (lane >> 4) * 8]));
            MMA_BF16(Sc[2 * p    ], a0, a1, a2, a3, r0, r2);
            MMA_BF16(Sc[2 * p + 1], a0, a1, a2, a3, r1, r3);
        }
    }

    const float scale = 0.17677669529663687f;
    int nr0 = n0 + r, nr1 = n0 + r + 8;
    int hq0 = (nr0 >= 32) ? 1 : 0, hq1 = (nr1 >= 32) ? 1 : 0;
    int wq  = (nr0 >> 2) & 1;
    int wm  = (q >= 2) ? 1 : 0;
    float sum0 = 0.f, sum1 = 0.f;
#pragma unroll
    for (int nt = 0; nt < 8; nt++) {
        int m0 = nt * 8 + 2 * q;
        int m1 = m0 + 1;
        int hm = (nt >= 4) ? 1 : 0;
        float pen0 = -100.f * (float)((fH & (hq0 ^ hm)) | (fW & (wq ^ wm)));
        float pen1 = -100.f * (float)((fH & (hq1 ^ hm)) | (fW & (wq ^ wm)));
        Sc[nt][0] = __expf(Sc[nt][0] * scale + rpb_s[rel_idx(nr0, m0)] + pen0);
        Sc[nt][1] = __expf(Sc[nt][1] * scale + rpb_s[rel_idx(nr0, m1)] + pen0);
        Sc[nt][2] = __expf(Sc[nt][2] * scale + rpb_s[rel_idx(nr1, m0)] + pen1);
        Sc[nt][3] = __expf(Sc[nt][3] * scale + rpb_s[rel_idx(nr1, m1)] + pen1);
        sum0 += Sc[nt][0] + Sc[nt][1];
        sum1 += Sc[nt][2] + Sc[nt][3];
    }
    sum0 += __shfl_xor_sync(0xffffffffu, sum0, 1);
    sum0 += __shfl_xor_sync(0xffffffffu, sum0, 2);
    sum1 += __shfl_xor_sync(0xffffffffu, sum1, 1);
    sum1 += __shfl_xor_sync(0xffffffffu, sum1, 2);
    float inv0 = 1.f / sum0, inv1 = 1.f / sum1;

    uint32_t Pa[4][4];
#pragma unroll
    for (int kt = 0; kt < 4; kt++) {
        Pa[kt][0] = packbf(Sc[2 * kt    ][0], Sc[2 * kt    ][1]);
        Pa[kt][1] = packbf(Sc[2 * kt    ][2], Sc[2 * kt    ][3]);
        Pa[kt][2] = packbf(Sc[2 * kt + 1][0], Sc[2 * kt + 1][1]);
        Pa[kt][3] = packbf(Sc[2 * kt + 1][2], Sc[2 * kt + 1][3]);
    }

    float Oc[4][4];
#pragma unroll
    for (int nt = 0; nt < 4; nt++)
#pragma unroll
        for (int e = 0; e < 4; e++) Oc[nt][e] = 0.f;

#pragma unroll
    for (int kt = 0; kt < 4; kt++) {
#pragma unroll
        for (int np = 0; np < 2; np++) {
            uint32_t b0, b1, b2, b3;
            ldsm_x4t(b0, b1, b2, b3, smem_u32(&vs[kt * 16 + (lane & 15)][np * 16 + (lane >> 4) * 8]));
            MMA_BF16(Oc[2 * np    ], Pa[kt][0], Pa[kt][1], Pa[kt][2], Pa[kt][3], b0, b1);
            MMA_BF16(Oc[2 * np + 1], Pa[kt][0], Pa[kt][1], Pa[kt][2], Pa[kt][3], b2, b3);
        }
    }

#pragma unroll
    for (int nt = 0; nt < 4; nt++) {
        int col = h * HD + nt * 8 + 2 * q;
        *(uint32_t*)(g_ao + (size_t)(base + nr0) * Cc + col) = packbf(Oc[nt][0] * inv0, Oc[nt][1] * inv0);
        *(uint32_t*)(g_ao + (size_t)(base + nr1) * Cc + col) = packbf(Oc[nt][2] * inv1, Oc[nt][3] * inv1);
    }
}

// ---------------- A-stationary bf16 GEMM for K=192 -------------------
// Tile M=128, full K in smem; loops N in chunks of 192. 384 thr, 12 warps.
// LNA: A is fp32, LayerNorm applied during staging.
// GATHER: A rows gathered via map_row (fuses shift+window partition).
// EPI: 0 bf16 store, 1 GELU->bf16, 2 proj scatter fp32 (+residual)
#define GSM_BYTES (128*200*2 + 2*32*200*2)   // 76800

template <int EPI, bool LNA, bool GATHER>
__global__ __launch_bounds__(384) void gemm192_kernel(
    const void* __restrict__ Ain, const bf16* __restrict__ Bw,
    const float* __restrict__ bias, void* __restrict__ outv,
    const float* __restrict__ src, const float* __restrict__ lng,
    const float* __restrict__ lnb, int N)
{
    extern __shared__ char smraw[];
    bf16 (*As)[200]      = reinterpret_cast<bf16(*)[200]>(smraw);
    bf16 (*Bs)[32][200]  = reinterpret_cast<bf16(*)[32][200]>(smraw + 128 * 200 * 2);

    int tid   = threadIdx.x;
    int lane  = tid & 31;
    int warp  = tid >> 5;
    int warpm = warp & 3;
    int warpn = warp >> 2;
    int bm    = blockIdx.x;

    auto copyB = [&](int buf, int nb, int s) {
#pragma unroll
        for (int c = tid; c < 768; c += 384) {
            int row = c / 24;
            int off = (c % 24) * 8;
            const bf16* gp = Bw + (size_t)(s * 32 + row) * N + nb * 192 + off;
            asm volatile("cp.async.ca.shared.global [%0], [%1], 16;"
                         :: "r"(smem_u32(&Bs[buf][row][off])), "l"(gp));
        }
        asm volatile("cp.async.commit_group;");
    };

    // prefetch first B slice
    copyB(0, 0, 0);

    // ---- stage A (full 128 x 192) ----
    if (LNA) {
        const float* A = (const float*)Ain;
        for (int i = warp; i < 128; i += 12) {
            int srcrow = GATHER ? map_row(bm * 128 + i) : (bm * 128 + i);
            const float* xr = A + (size_t)srcrow * Cc;
            float v[6]; float s = 0.f, qq = 0.f;
#pragma unroll
            for (int j = 0; j < 6; j++) {
                v[j] = xr[lane + 32 * j];
                s += v[j]; qq += v[j] * v[j];
            }
#pragma unroll
            for (int o = 16; o > 0; o >>= 1) {
                s  += __shfl_xor_sync(0xffffffffu, s,  o);
                qq += __shfl_xor_sync(0xffffffffu, qq, o);
            }
            float mu = s * (1.f / Cc);
            float rs = rsqrtf(qq * (1.f / Cc) - mu * mu + 1e-5f);
#pragma unroll
            for (int j = 0; j < 6; j++) {
                int e = lane + 32 * j;
                As[i][e] = __float2bfloat16_rn((v[j] - mu) * rs * lng[e] + lnb[e]);
            }
        }
    } else {
        const bf16* A = (const bf16*)Ain;
#pragma unroll
        for (int c = tid; c < 3072; c += 384) {
            int row = c / 24;
            int off = (c % 24) * 8;
            const bf16* gp = A + (size_t)(bm * 128 + row) * Cc + off;
            asm volatile("cp.async.ca.shared.global [%0], [%1], 16;"
                         :: "r"(smem_u32(&As[row][off])), "l"(gp));
        }
        asm volatile("cp.async.commit_group;");
    }

    int r  = lane >> 2;
    int q2 = (lane & 3) * 2;
    int nchunks = N / 192;

    for (int nb = 0; nb < nchunks; nb++) {
        if (nb > 0) copyB(0, nb, 0);

        float acc[2][8][4];
#pragma unroll
        for (int mi = 0; mi < 2; mi++)
#pragma unroll
            for (int ni = 0; ni < 8; ni++)
#pragma unroll
                for (int e = 0; e < 4; e++) acc[mi][ni][e] = 0.f;

        int buf = 0;
#pragma unroll
        for (int s = 0; s < 6; s++) {
            if (s < 5) {
                copyB(buf ^ 1, nb, s + 1);
                asm volatile("cp.async.wait_group 1;");
            } else {
                asm volatile("cp.async.wait_group 0;");
            }
            __syncthreads();

#pragma unroll
            for (int kc = 0; kc < 2; kc++) {
                uint32_t a[2][4];
#pragma unroll
                for (int mi = 0; mi < 2; mi++)
                    ldsm_x4(a[mi][0], a[mi][1], a[mi][2], a[mi][3],
                            smem_u32(&As[warpm * 32 + mi * 16 + (lane & 15)][s * 32 + kc * 16 + (lane >> 4) * 8]));
                uint32_t bf[8][2];
#pragma unroll
                for (int p = 0; p < 4; p++) {
                    uint32_t r0, r1, r2, r3;
                    ldsm_x4t(r0, r1, r2, r3,
                             smem_u32(&Bs[buf][kc * 16 + (lane & 15)][warpn * 64 + p * 16 + (lane >> 4) * 8]));
                    bf[2 * p][0] = r0; bf[2 * p][1] = r1;
                    bf[2 * p + 1][0] = r2; bf[2 * p + 1][1] = r3;
                }
#pragma unroll
                for (int mi = 0; mi < 2; mi++)
#pragma unroll
                    for (int ni = 0; ni < 8; ni++)
                        MMA_BF16(acc[mi][ni], a[mi][0], a[mi][1], a[mi][2], a[mi][3],
                                 bf[ni][0], bf[ni][1]);
            }
            __syncthreads();
            buf ^= 1;
        }

        // ---- epilogue for this N-chunk ----
#pragma unroll
        for (int mi = 0; mi < 2; mi++) {
            int row0 = bm * 128 + warpm * 32 + mi * 16 + r;
#pragma unroll
            for (int ni = 0; ni < 8; ni++) {
                int col = nb * 192 + warpn * 64 + ni * 8 + q2;
                float b0 = bias[col], b1 = bias[col + 1];
                float v0 = acc[mi][ni][0] + b0, v1 = acc[mi][ni][1] + b1;
                float v2 = acc[mi][ni][2] + b0, v3 = acc[mi][ni][3] + b1;
                if (EPI == 0) {
                    bf16* o = (bf16*)outv;
                    *(uint32_t*)(o + (size_t)row0 * N + col)       = packbf(v0, v1);
                    *(uint32_t*)(o + (size_t)(row0 + 8) * N + col) = packbf(v2, v3);
                } else if (EPI == 1) {
                    bf16* o = (bf16*)outv;
                    v0 = 0.5f * v0 * (1.f + erff(v0 * 0.7071067811865475f));
                    v1 = 0.5f * v1 * (1.f + erff(v1 * 0.7071067811865475f));
                    v2 = 0.5f * v2 * (1.f + erff(v2 * 0.7071067811865475f));
                    v3 = 0.5f * v3 * (1.f + erff(v3 * 0.7071067811865475f));
                    *(uint32_t*)(o + (size_t)row0 * N + col)       = packbf(v0, v1);
                    *(uint32_t*)(o + (size_t)(row0 + 8) * N + col) = packbf(v2, v3);
                } else {
                    float* o = (float*)outv;
                    int dr0 = map_row(row0), dr1 = map_row(row0 + 8);
                    size_t o0 = (size_t)dr0 * Cc + col, o1 = (size_t)dr1 * Cc + col;
                    *(float2*)(o + o0) = make_float2(src[o0] + v0, src[o0 + 1] + v1);
                    *(float2*)(o + o1) = make_float2(src[o1] + v2, src[o1 + 1] + v3);
                }
            }
        }
    }
}

// ---------------- streaming bf16 GEMM (fc2, K=768) -------------------
#define AS_STR 40
#define BS_STR 200

__global__ __launch_bounds__(384) void gemm_fc2_kernel(
    const bf16* __restrict__ A, const bf16* __restrict__ B,
    const float* __restrict__ bias, float* __restrict__ out,
    int M, int N, int K)
{
    __shared__ bf16 As[2][128][AS_STR];
    __shared__ bf16 Bs[2][32][BS_STR];

    int tid   = threadIdx.x;
    int lane  = tid & 31;
    int warp  = tid >> 5;
    int warpm = warp & 3;
    int warpn = warp >> 2;
    int bm = blockIdx.x;

    float acc[2][8][4];
#pragma unroll
    for (int mi = 0; mi < 2; mi++)
#pragma unroll
        for (int ni = 0; ni < 8; ni++)
#pragma unroll
            for (int e = 0; e < 4; e++) acc[mi][ni][e] = 0.f;

    auto copy_tile = [&](int buf, int k0) {
#pragma unroll
        for (int c = tid; c < 512; c += 384) {
            int row = c >> 2;
            int off = (c & 3) * 8;
            const bf16* gp = A + (size_t)(bm * 128 + row) * K + k0 + off;
            asm volatile("cp.async.ca.shared.global [%0], [%1], 16;"
                         :: "r"(smem_u32(&As[buf][row][off])), "l"(gp));
        }
#pragma unroll
        for (int c = tid; c < 768; c += 384) {
            int row = c / 24;
            int col = (c % 24) * 8;
            const bf16* gp = B + (size_t)(k0 + row) * N + col;
            asm volatile("cp.async.ca.shared.global [%0], [%1], 16;"
                         :: "r"(smem_u32(&Bs[buf][row][col])), "l"(gp));
        }
        asm volatile("cp.async.commit_group;");
    };

    copy_tile(0, 0);

    int buf = 0;
    for (int k0 = 0; k0 < K; k0 += 32, buf ^= 1) {
        if (k0 + 32 < K) {
            copy_tile(buf ^ 1, k0 + 32);
            asm volatile("cp.async.wait_group 1;");
        } else {
            asm volatile("cp.async.wait_group 0;");
        }
        __syncthreads();

#pragma unroll
        for (int kc = 0; kc < 2; kc++) {
            uint32_t a[2][4];
#pragma unroll
            for (int mi = 0; mi < 2; mi++)
                ldsm_x4(a[mi][0], a[mi][1], a[mi][2], a[mi][3],
                        smem_u32(&As[buf][warpm * 32 + mi * 16 + (lane & 15)][kc * 16 + (lane >> 4) * 8]));
            uint32_t bf[8][2];
#pragma unroll
            for (int p = 0; p < 4; p++) {
                uint32_t r0, r1, r2, r3;
                ldsm_x4t(r0, r1, r2, r3,
                         smem_u32(&Bs[buf][kc * 16 + (lane & 15)][warpn * 64 + p * 16 + (lane >> 4) * 8]));
                bf[2 * p][0] = r0; bf[2 * p][1] = r1;
                bf[2 * p + 1][0] = r2; bf[2 * p + 1][1] = r3;
            }
#pragma unroll
            for (int mi = 0; mi < 2; mi++)
#pragma unroll
                for (int ni = 0; ni < 8; ni++)
                    MMA_BF16(acc[mi][ni], a[mi][0], a[mi][1], a[mi][2], a[mi][3],
                             bf[ni][0], bf[ni][1]);
        }
        __syncthreads();
    }

    int r  = lane >> 2;
    int q2 = (lane & 3) * 2;
#pragma unroll
    for (int mi = 0; mi < 2; mi++) {
        int row0 = bm * 128 + warpm * 32 + mi * 16 + r;
#pragma unroll
        for (int ni = 0; ni < 8; ni++) {
            int col = warpn * 64 + ni * 8 + q2;
            float b0 = bias[col], b1 = bias[col + 1];
            size_t o0 = (size_t)row0 * N + col, o1 = (size_t)(row0 + 8) * N + col;
            out[o0]     += acc[mi][ni][0] + b0;
            out[o0 + 1] += acc[mi][ni][1] + b1;
            out[o1]     += acc[mi][ni][2] + b0;
            out[o1 + 1] += acc[mi][ni][3] + b1;
        }
    }
}

// ---------------- launch ----------------
extern "C" void kernel_launch(void* const* d_in, const int* in_sizes, int n_in,
                              void* d_out, int out_size)
{
    (void)in_sizes; (void)n_in; (void)out_size;
    const float* x    = (const float*)d_in[0];
    const float* x1   = (const float*)d_in[1];
    const float* n1g  = (const float*)d_in[3];
    const float* n1b  = (const float*)d_in[4];
    const float* qw   = (const float*)d_in[5];
    const float* qb   = (const float*)d_in[6];
    const float* kvw  = (const float*)d_in[7];
    const float* kvb  = (const float*)d_in[8];
    const float* rpb  = (const float*)d_in[9];
    const float* pw   = (const float*)d_in[10];
    const float* pb   = (const float*)d_in[11];
    const float* n2g  = (const float*)d_in[12];
    const float* n2b  = (const float*)d_in[13];
    const float* f1w  = (const float*)d_in[14];
    const float* f1b  = (const float*)d_in[15];
    const float* f2w  = (const float*)d_in[16];
    const float* f2b  = (const float*)d_in[17];
    float* out = (float*)d_out;

    bf16 *q, *kv, *ao, *h;
    cudaGetSymbolAddress((void**)&q,   g_q);
    cudaGetSymbolAddress((void**)&kv,  g_kv);
    cudaGetSymbolAddress((void**)&ao,  g_ao);
    cudaGetSymbolAddress((void**)&h,   g_h);
    bf16 *qwb, *kvwb, *pwb, *f1wb, *f2wb;
    cudaGetSymbolAddress((void**)&qwb,  g_qwb);
    cudaGetSymbolAddress((void**)&kvwb, g_kvwb);
    cudaGetSymbolAddress((void**)&pwb,  g_pwb);
    cudaGetSymbolAddress((void**)&f1wb, g_f1wb);
    cudaGetSymbolAddress((void**)&f2wb, g_f2wb);

    cudaFuncSetAttribute(gemm192_kernel<0, true,  true >, cudaFuncAttributeMaxDynamicSharedMemorySize, GSM_BYTES);
    cudaFuncSetAttribute(gemm192_kernel<2, false, false>, cudaFuncAttributeMaxDynamicSharedMemorySize, GSM_BYTES);
    cudaFuncSetAttribute(gemm192_kernel<1, true,  false>, cudaFuncAttributeMaxDynamicSharedMemorySize, GSM_BYTES);

    cvt_all_kernel<<<(W5 + 255) / 256, 256>>>(qw, kvw, pw, f1w, f2w);
    // kv = LN1(shift/window(x)) @ kv_w + kv_b   (LN1 fused into A staging)
    gemm192_kernel<0, true, true ><<<MTOK / 128, 384, GSM_BYTES>>>(x,  kvwb, kvb, kv, nullptr, n1g, n1b, 384);
    // q  = LN1(shift/window(x1)) @ q_w + q_b
    gemm192_kernel<0, true, true ><<<MTOK / 128, 384, GSM_BYTES>>>(x1, qwb,  qb,  q,  nullptr, n1g, n1b, 192);
    attn_kernel<<<BW * HEADS, 128>>>(rpb);
    gemm192_kernel<2, false, false><<<MTOK / 128, 384, GSM_BYTES>>>(ao, pwb, pb, out, x, nullptr, nullptr, 192);
    gemm192_kernel<1, true,  false><<<MTOK / 128, 384, GSM_BYTES>>>(out, f1wb, f1b, h, nullptr, n2g, n2b, 768);
    gemm_fc2_kernel<<<MTOK / 128, 384>>>(h, f2wb, f2b, out, MTOK, Cc, HID);
}

// round 9
// speedup vs baseline: 1.1679x; 1.1679x over previous
#include <cuda_runtime.h>
#include <cuda_bf16.h>
#include <math.h>
#include <stdint.h>

// ---------------- problem constants ----------------
#define Bz    4
#define Hh    128
#define Wfull 256
#define Cc    192
#define Ll    (Hh*Wfull)
#define HEADS 6
#define HD    32
#define NWIN  512
#define BW    (Bz*NWIN)         // 2048 windows
#define MTOK  (BW*64)           // 131072 window tokens
#define HID   768

typedef __nv_bfloat16 bf16;

// ---------------- scratch ----------------
__device__ bf16  g_xw [MTOK*Cc];
__device__ bf16  g_x1w[MTOK*Cc];
__device__ bf16  g_q  [MTOK*Cc];
__device__ bf16  g_kv [MTOK*2*Cc];
__device__ bf16  g_ao [MTOK*Cc];
__device__ bf16  g_h  [MTOK*HID];
// bf16 weights
__device__ bf16  g_qwb [Cc*Cc];
__device__ bf16  g_kvwb[Cc*2*Cc];
__device__ bf16  g_pwb [Cc*Cc];
__device__ bf16  g_f1wb[Cc*HID];
__device__ bf16  g_f2wb[HID*Cc];

__device__ __forceinline__ int map_row(int t) {
    int b_  = t >> 6;
    int n   = t & 63;
    int b   = b_ >> 9;
    int win = b_ & 511;
    int hi  = win >> 5;
    int wi  = win & 31;
    int r   = n >> 3, c = n & 7;
    int sh  = (hi * 8 + r + 4) & (Hh - 1);
    int sw  = (wi * 8 + c + 4) & (Wfull - 1);
    return b * Ll + sh * Wfull + sw;
}

__device__ __forceinline__ uint32_t smem_u32(const void* p) {
    return (uint32_t)__cvta_generic_to_shared(p);
}
__device__ __forceinline__ uint32_t packbf(float x, float y) {
    __nv_bfloat162 t = __floats2bfloat162_rn(x, y);
    return *reinterpret_cast<uint32_t*>(&t);
}
__device__ __forceinline__ void ldsm_x4(uint32_t& r0, uint32_t& r1, uint32_t& r2, uint32_t& r3, uint32_t a) {
    asm volatile("ldmatrix.sync.aligned.m8n8.x4.shared.b16 {%0,%1,%2,%3}, [%4];"
                 : "=r"(r0), "=r"(r1), "=r"(r2), "=r"(r3) : "r"(a));
}
__device__ __forceinline__ void ldsm_x4t(uint32_t& r0, uint32_t& r1, uint32_t& r2, uint32_t& r3, uint32_t a) {
    asm volatile("ldmatrix.sync.aligned.m8n8.x4.trans.shared.b16 {%0,%1,%2,%3}, [%4];"
                 : "=r"(r0), "=r"(r1), "=r"(r2), "=r"(r3) : "r"(a));
}
#define MMA_BF16(C, A0,A1,A2,A3, B0,B1) \
    asm volatile("mma.sync.aligned.m16n8k16.row.col.f32.bf16.bf16.f32 " \
        "{%0,%1,%2,%3},{%4,%5,%6,%7},{%8,%9},{%0,%1,%2,%3};" \
        : "+f"(C[0]), "+f"(C[1]), "+f"(C[2]), "+f"(C[3]) \
        : "r"(A0), "r"(A1), "r"(A2), "r"(A3), "r"(B0), "r"(B1))

// ---------------- all weights fp32 -> bf16, one launch ----------------
#define W1 (Cc*Cc)
#define W2 (W1 + Cc*2*Cc)
#define W3 (W2 + Cc*Cc)
#define W4 (W3 + Cc*HID)
#define W5 (W4 + HID*Cc)
__global__ void cvt_all_kernel(const float* __restrict__ qw, const float* __restrict__ kvw,
                               const float* __restrict__ pw, const float* __restrict__ f1w,
                               const float* __restrict__ f2w) {
    int i = blockIdx.x * 256 + threadIdx.x;
    if (i < W1)      g_qwb [i]      = __float2bfloat16_rn(qw [i]);
    else if (i < W2) g_kvwb[i - W1] = __float2bfloat16_rn(kvw[i - W1]);
    else if (i < W3) g_pwb [i - W2] = __float2bfloat16_rn(pw [i - W2]);
    else if (i < W4) g_f1wb[i - W3] = __float2bfloat16_rn(f1w[i - W3]);
    else if (i < W5) g_f2wb[i - W4] = __float2bfloat16_rn(f2w[i - W4]);
}

// ---------------- LN1 + roll + window partition (bf16 out) ----------
__global__ __launch_bounds__(256) void ln1_gather_kernel(
    const float* __restrict__ x, const float* __restrict__ x1,
    const float* __restrict__ g, const float* __restrict__ b)
{
    int warp = (blockIdx.x * blockDim.x + threadIdx.x) >> 5;
    int lane = threadIdx.x & 31;
    if (warp >= MTOK) return;
    int src = map_row(warp);
    const float* xr  = x  + (size_t)src * Cc;
    const float* x1r = x1 + (size_t)src * Cc;

    float v0[6], v1[6];
    float s0 = 0.f, s1 = 0.f, q0 = 0.f, q1 = 0.f;
#pragma unroll
    for (int j = 0; j < 6; j++) {
        v0[j] = xr [lane + 32 * j];
        v1[j] = x1r[lane + 32 * j];
        s0 += v0[j]; q0 += v0[j] * v0[j];
        s1 += v1[j]; q1 += v1[j] * v1[j];
    }
#pragma unroll
    for (int o = 16; o > 0; o >>= 1) {
        s0 += __shfl_xor_sync(0xffffffffu, s0, o);
        q0 += __shfl_xor_sync(0xffffffffu, q0, o);
        s1 += __shfl_xor_sync(0xffffffffu, s1, o);
        q1 += __shfl_xor_sync(0xffffffffu, q1, o);
    }
    float mu0 = s0 * (1.f / Cc), mu1 = s1 * (1.f / Cc);
    float r0 = rsqrtf(q0 * (1.f / Cc) - mu0 * mu0 + 1e-5f);
    float r1 = rsqrtf(q1 * (1.f / Cc) - mu1 * mu1 + 1e-5f);
    size_t ob = (size_t)warp * Cc;
#pragma unroll
    for (int j = 0; j < 6; j++) {
        int e = lane + 32 * j;
        float ge = g[e], be = b[e];
        g_xw [ob + e] = __float2bfloat16_rn((v0[j] - mu0) * r0 * ge + be);
        g_x1w[ob + e] = __float2bfloat16_rn((v1[j] - mu1) * r1 * ge + be);
    }
}

// ---------------- attention: bf16 mma, analytic mask --------------
__device__ __forceinline__ int rel_idx(int n, int m) {
    return ((n >> 3) - (m >> 3) + 7) * 15 + ((n & 7) - (m & 7) + 7);
}

__global__ __launch_bounds__(128) void attn_kernel(const float* __restrict__ rpb_table)
{
    __shared__ bf16  qs[64][40];
    __shared__ bf16  ks[64][40];
    __shared__ bf16  vs[64][40];
    __shared__ float rpb_s[225];

    int bx   = blockIdx.x;
    int h    = bx % HEADS;
    int w    = bx / HEADS;
    int tid  = threadIdx.x;
    int lane = tid & 31;
    int warp = tid >> 5;
    int base = w * 64;

    int fH = (((w >> 5) & 15) == 15) ? 1 : 0;
    int fW = ((w & 31) == 31) ? 1 : 0;

#pragma unroll
    for (int i = 0; i < 2; i++) {
        int c   = tid + i * 128;
        int row = c >> 2;
        int off = (c & 3) * 8;
        const bf16* gq = g_q  + (size_t)(base + row) * Cc  + h * HD + off;
        const bf16* gk = g_kv + (size_t)(base + row) * 384 + h * HD + off;
        const bf16* gv = g_kv + (size_t)(base + row) * 384 + 192 + h * HD + off;
        asm volatile("cp.async.ca.shared.global [%0], [%1], 16;" :: "r"(smem_u32(&qs[row][off])), "l"(gq));
        asm volatile("cp.async.ca.shared.global [%0], [%1], 16;" :: "r"(smem_u32(&ks[row][off])), "l"(gk));
        asm volatile("cp.async.ca.shared.global [%0], [%1], 16;" :: "r"(smem_u32(&vs[row][off])), "l"(gv));
    }
    asm volatile("cp.async.commit_group;");
    for (int i = tid; i < 225; i += 128)
        rpb_s[i] = __ldg(rpb_table + i * HEADS + h);
    asm volatile("cp.async.wait_group 0;");
    __syncthreads();

    int r  = lane >> 2;
    int q  = lane & 3;
    int n0 = warp * 16;

    float Sc[8][4];
#pragma unroll
    for (int nt = 0; nt < 8; nt++)
#pragma unroll
        for (int e = 0; e < 4; e++) Sc[nt][e] = 0.f;

#pragma unroll
    for (int kc = 0; kc < 2; kc++) {
        uint32_t a0, a1, a2, a3;
        ldsm_x4(a0, a1, a2, a3, smem_u32(&qs[n0 + (lane & 15)][kc * 16 + (lane >> 4) * 8]));
#pragma unroll
        for (int p = 0; p < 4; p++) {
            uint32_t r0, r1, r2, r3;
            ldsm_x4(r0, r1, r2, r3, smem_u32(&ks[p * 16 + (lane & 15)][kc * 16 + (lane >> 4) * 8]));
            MMA_BF16(Sc[2 * p    ], a0, a1, a2, a3, r0, r2);
            MMA_BF16(Sc[2 * p + 1], a0, a1, a2, a3, r1, r3);
        }
    }

    const float scale = 0.17677669529663687f;
    int nr0 = n0 + r, nr1 = n0 + r + 8;
    int hq0 = (nr0 >= 32) ? 1 : 0, hq1 = (nr1 >= 32) ? 1 : 0;
    int wq  = (nr0 >> 2) & 1;
    int wm  = (q >= 2) ? 1 : 0;
    float sum0 = 0.f, sum1 = 0.f;
#pragma unroll
    for (int nt = 0; nt < 8; nt++) {
        int m0 = nt * 8 + 2 * q;
        int m1 = m0 + 1;
        int hm = (nt >= 4) ? 1 : 0;
        float pen0 = -100.f * (float)((fH & (hq0 ^ hm)) | (fW & (wq ^ wm)));
        float pen1 = -100.f * (float)((fH & (hq1 ^ hm)) | (fW & (wq ^ wm)));
        Sc[nt][0] = __expf(Sc[nt][0] * scale + rpb_s[rel_idx(nr0, m0)] + pen0);
        Sc[nt][1] = __expf(Sc[nt][1] * scale + rpb_s[rel_idx(nr0, m1)] + pen0);
        Sc[nt][2] = __expf(Sc[nt][2] * scale + rpb_s[rel_idx(nr1, m0)] + pen1);
        Sc[nt][3] = __expf(Sc[nt][3] * scale + rpb_s[rel_idx(nr1, m1)] + pen1);
        sum0 += Sc[nt][0] + Sc[nt][1];
        sum1 += Sc[nt][2] + Sc[nt][3];
    }
    sum0 += __shfl_xor_sync(0xffffffffu, sum0, 1);
    sum0 += __shfl_xor_sync(0xffffffffu, sum0, 2);
    sum1 += __shfl_xor_sync(0xffffffffu, sum1, 1);
    sum1 += __shfl_xor_sync(0xffffffffu, sum1, 2);
    float inv0 = 1.f / sum0, inv1 = 1.f / sum1;

    uint32_t Pa[4][4];
#pragma unroll
    for (int kt = 0; kt < 4; kt++) {
        Pa[kt][0] = packbf(Sc[2 * kt    ][0], Sc[2 * kt    ][1]);
        Pa[kt][1] = packbf(Sc[2 * kt    ][2], Sc[2 * kt    ][3]);
        Pa[kt][2] = packbf(Sc[2 * kt + 1][0], Sc[2 * kt + 1][1]);
        Pa[kt][3] = packbf(Sc[2 * kt + 1][2], Sc[2 * kt + 1][3]);
    }

    float Oc[4][4];
#pragma unroll
    for (int nt = 0; nt < 4; nt++)
#pragma unroll
        for (int e = 0; e < 4; e++) Oc[nt][e] = 0.f;

#pragma unroll
    for (int kt = 0; kt < 4; kt++) {
#pragma unroll
        for (int np = 0; np < 2; np++) {
            uint32_t b0, b1, b2, b3;
            ldsm_x4t(b0, b1, b2, b3, smem_u32(&vs[kt * 16 + (lane & 15)][np * 16 + (lane >> 4) * 8]));
            MMA_BF16(Oc[2 * np    ], Pa[kt][0], Pa[kt][1], Pa[kt][2], Pa[kt][3], b0, b1);
            MMA_BF16(Oc[2 * np + 1], Pa[kt][0], Pa[kt][1], Pa[kt][2], Pa[kt][3], b2, b3);
        }
    }

#pragma unroll
    for (int nt = 0; nt < 4; nt++) {
        int col = h * HD + nt * 8 + 2 * q;
        *(uint32_t*)(g_ao + (size_t)(base + nr0) * Cc + col) = packbf(Oc[nt][0] * inv0, Oc[nt][1] * inv0);
        *(uint32_t*)(g_ao + (size_t)(base + nr1) * Cc + col) = packbf(Oc[nt][2] * inv1, Oc[nt][3] * inv1);
    }
}

// ---------------- A-stationary bf16 GEMM for K=192, M=64 tile --------
// 256 thr (8 warps: 2 warpm x 4 warpn(48 cols)); 3-buffer B ring,
// single __syncthreads per stage; targets 3 CTAs/SM.
// EPI: 0 bf16 store, 1 GELU->bf16, 2 proj scatter fp32 (+residual)
#define GSM_BYTES (64*200*2 + 3*32*200*2)   // 25600 + 38400 = 64000

template <int EPI, bool LNA>
__global__ __launch_bounds__(256, 3) void gemm192_kernel(
    const void* __restrict__ Ain, const bf16* __restrict__ Bw,
    const float* __restrict__ bias, void* __restrict__ outv,
    const float* __restrict__ src, const float* __restrict__ lng,
    const float* __restrict__ lnb, int N)
{
    extern __shared__ char smraw[];
    bf16 (*As)[200]      = reinterpret_cast<bf16(*)[200]>(smraw);
    bf16 (*Bs)[32][200]  = reinterpret_cast<bf16(*)[32][200]>(smraw + 64 * 200 * 2);

    int tid   = threadIdx.x;
    int lane  = tid & 31;
    int warp  = tid >> 5;
    int warpm = warp & 1;          // 0..1 -> 32 rows
    int warpn = warp >> 1;         // 0..3 -> 48 cols
    int bm    = blockIdx.x;

    int nchunks = N / 192;
    int S_tot   = nchunks * 6;

    auto copyB = [&](int st) {
        int buf = st % 3;
        int nb  = st / 6, s = st % 6;
#pragma unroll
        for (int c = tid; c < 768; c += 256) {
            int row = c / 24;
            int off = (c % 24) * 8;
            const bf16* gp = Bw + (size_t)(s * 32 + row) * N + nb * 192 + off;
            asm volatile("cp.async.ca.shared.global [%0], [%1], 16;"
                         :: "r"(smem_u32(&Bs[buf][row][off])), "l"(gp));
        }
        asm volatile("cp.async.commit_group;");
    };

    // ---- prologue ----
    if (LNA) {
        copyB(0);
        copyB(1);
        const float* A = (const float*)Ain;
        for (int i = warp; i < 64; i += 8) {
            const float* xr = A + (size_t)(bm * 64 + i) * Cc;
            float v[6]; float s = 0.f, qq = 0.f;
#pragma unroll
            for (int j = 0; j < 6; j++) {
                v[j] = xr[lane + 32 * j];
                s += v[j]; qq += v[j] * v[j];
            }
#pragma unroll
            for (int o = 16; o > 0; o >>= 1) {
                s  += __shfl_xor_sync(0xffffffffu, s,  o);
                qq += __shfl_xor_sync(0xffffffffu, qq, o);
            }
            float mu = s * (1.f / Cc);
            float rs = rsqrtf(qq * (1.f / Cc) - mu * mu + 1e-5f);
#pragma unroll
            for (int j = 0; j < 6; j++) {
                int e = lane + 32 * j;
                As[i][e] = __float2bfloat16_rn((v[j] - mu) * rs * lng[e] + lnb[e]);
            }
        }
    } else {
        // A group FIRST so wait_group 1 guarantees it done at stage 0
        const bf16* A = (const bf16*)Ain;
#pragma unroll
        for (int c = tid; c < 1536; c += 256) {
            int row = c / 24;
            int off = (c % 24) * 8;
            const bf16* gp = A + (size_t)(bm * 64 + row) * Cc + off;
            asm volatile("cp.async.ca.shared.global [%0], [%1], 16;"
                         :: "r"(smem_u32(&As[row][off])), "l"(gp));
        }
        asm volatile("cp.async.commit_group;");
        copyB(0);
        copyB(1);
    }

    int r  = lane >> 2;
    int q2 = (lane & 3) * 2;

    for (int nb = 0; nb < nchunks; nb++) {
        float acc[2][6][4];
#pragma unroll
        for (int mi = 0; mi < 2; mi++)
#pragma unroll
            for (int ni = 0; ni < 6; ni++)
#pragma unroll
                for (int e = 0; e < 4; e++) acc[mi][ni][e] = 0.f;

#pragma unroll 1
        for (int s = 0; s < 6; s++) {
            int st = nb * 6 + s;
            asm volatile("cp.async.wait_group 1;");
            __syncthreads();
            if (st + 2 < S_tot) copyB(st + 2);
            else asm volatile("cp.async.commit_group;");
            int buf = st % 3;

#pragma unroll
            for (int kc = 0; kc < 2; kc++) {
                uint32_t a[2][4];
#pragma unroll
                for (int mi = 0; mi < 2; mi++)
                    ldsm_x4(a[mi][0], a[mi][1], a[mi][2], a[mi][3],
                            smem_u32(&As[warpm * 32 + mi * 16 + (lane & 15)][s * 32 + kc * 16 + (lane >> 4) * 8]));
                uint32_t bfg[6][2];
#pragma unroll
                for (int p = 0; p < 3; p++) {
                    uint32_t r0, r1, r2, r3;
                    ldsm_x4t(r0, r1, r2, r3,
                             smem_u32(&Bs[buf][kc * 16 + (lane & 15)][warpn * 48 + p * 16 + (lane >> 4) * 8]));
                    bfg[2 * p][0] = r0; bfg[2 * p][1] = r1;
                    bfg[2 * p + 1][0] = r2; bfg[2 * p + 1][1] = r3;
                }
#pragma unroll
                for (int mi = 0; mi < 2; mi++)
#pragma unroll
                    for (int ni = 0; ni < 6; ni++)
                        MMA_BF16(acc[mi][ni], a[mi][0], a[mi][1], a[mi][2], a[mi][3],
                                 bfg[ni][0], bfg[ni][1]);
            }
        }

        // ---- epilogue for this N-chunk (next loads already in flight) ----
#pragma unroll
        for (int mi = 0; mi < 2; mi++) {
            int row0 = bm * 64 + warpm * 32 + mi * 16 + r;
#pragma unroll
            for (int ni = 0; ni < 6; ni++) {
                int col = nb * 192 + warpn * 48 + ni * 8 + q2;
                float b0 = bias[col], b1 = bias[col + 1];
                float v0 = acc[mi][ni][0] + b0, v1 = acc[mi][ni][1] + b1;
                float v2 = acc[mi][ni][2] + b0, v3 = acc[mi][ni][3] + b1;
                if (EPI == 0) {
                    bf16* o = (bf16*)outv;
                    *(uint32_t*)(o + (size_t)row0 * N + col)       = packbf(v0, v1);
                    *(uint32_t*)(o + (size_t)(row0 + 8) * N + col) = packbf(v2, v3);
                } else if (EPI == 1) {
                    bf16* o = (bf16*)outv;
                    v0 = 0.5f * v0 * (1.f + erff(v0 * 0.7071067811865475f));
                    v1 = 0.5f * v1 * (1.f + erff(v1 * 0.7071067811865475f));
                    v2 = 0.5f * v2 * (1.f + erff(v2 * 0.7071067811865475f));
                    v3 = 0.5f * v3 * (1.f + erff(v3 * 0.7071067811865475f));
                    *(uint32_t*)(o + (size_t)row0 * N + col)       = packbf(v0, v1);
                    *(uint32_t*)(o + (size_t)(row0 + 8) * N + col) = packbf(v2, v3);
                } else {
                    float* o = (float*)outv;
                    int dr0 = map_row(row0), dr1 = map_row(row0 + 8);
                    size_t o0 = (size_t)dr0 * Cc + col, o1 = (size_t)dr1 * Cc + col;
                    *(float2*)(o + o0) = make_float2(src[o0] + v0, src[o0 + 1] + v1);
                    *(float2*)(o + o1) = make_float2(src[o1] + v2, src[o1 + 1] + v3);
                }
            }
        }
    }
}

// ---------------- streaming bf16 GEMM (fc2, K=768), M=64 tile --------
#define F2SM_BYTES (3*64*40*2 + 3*32*200*2)   // 15360 + 38400 = 53760

__global__ __launch_bounds__(256, 3) void gemm_fc2_kernel(
    const bf16* __restrict__ A, const bf16* __restrict__ B,
    const float* __restrict__ bias, float* __restrict__ out)
{
    extern __shared__ char smraw[];
    bf16 (*As)[64][40]   = reinterpret_cast<bf16(*)[64][40]>(smraw);
    bf16 (*Bs)[32][200]  = reinterpret_cast<bf16(*)[32][200]>(smraw + 3 * 64 * 40 * 2);

    const int N = Cc, K = HID;
    int tid   = threadIdx.x;
    int lane  = tid & 31;
    int warp  = tid >> 5;
    int warpm = warp & 1;
    int warpn = warp >> 1;
    int bm = blockIdx.x;

    const int S_tot = K / 32;   // 24

    auto copyAB = [&](int st) {
        int buf = st % 3;
        int k0  = st * 32;
#pragma unroll
        for (int c = tid; c < 256; c += 256) {
            int row = c >> 2;
            int off = (c & 3) * 8;
            const bf16* gp = A + (size_t)(bm * 64 + row) * K + k0 + off;
            asm volatile("cp.async.ca.shared.global [%0], [%1], 16;"
                         :: "r"(smem_u32(&As[buf][row][off])), "l"(gp));
        }
#pragma unroll
        for (int c = tid; c < 768; c += 256) {
            int row = c / 24;
            int col = (c % 24) * 8;
            const bf16* gp = B + (size_t)(k0 + row) * N + col;
            asm volatile("cp.async.ca.shared.global [%0], [%1], 16;"
                         :: "r"(smem_u32(&Bs[buf][row][col])), "l"(gp));
        }
        asm volatile("cp.async.commit_group;");
    };

    copyAB(0);
    copyAB(1);

    float acc[2][6][4];
#pragma unroll
    for (int mi = 0; mi < 2; mi++)
#pragma unroll
        for (int ni = 0; ni < 6; ni++)
#pragma unroll
            for (int e = 0; e < 4; e++) acc[mi][ni][e] = 0.f;

#pragma unroll 1
    for (int st = 0; st < S_tot; st++) {
        asm volatile("cp.async.wait_group 1;");
        __syncthreads();
        if (st + 2 < S_tot) copyAB(st + 2);
        else asm volatile("cp.async.commit_group;");
        int buf = st % 3;

#pragma unroll
        for (int kc = 0; kc < 2; kc++) {
            uint32_t a[2][4];
#pragma unroll
            for (int mi = 0; mi < 2; mi++)
                ldsm_x4(a[mi][0], a[mi][1], a[mi][2], a[mi][3],
                        smem_u32(&As[buf][warpm * 32 + mi * 16 + (lane & 15)][kc * 16 + (lane >> 4) * 8]));
            uint32_t bfg[6][2];
#pragma unroll
            for (int p = 0; p < 3; p++) {
                uint32_t r0, r1, r2, r3;
                ldsm_x4t(r0, r1, r2, r3,
                         smem_u32(&Bs[buf][kc * 16 + (lane & 15)][warpn * 48 + p * 16 + (lane >> 4) * 8]));
                bfg[2 * p][0] = r0; bfg[2 * p][1] = r1;
                bfg[2 * p + 1][0] = r2; bfg[2 * p + 1][1] = r3;
            }
#pragma unroll
            for (int mi = 0; mi < 2; mi++)
#pragma unroll
                for (int ni = 0; ni < 6; ni++)
                    MMA_BF16(acc[mi][ni], a[mi][0], a[mi][1], a[mi][2], a[mi][3],
                             bfg[ni][0], bfg[ni][1]);
        }
    }

    int r  = lane >> 2;
    int q2 = (lane & 3) * 2;
#pragma unroll
    for (int mi = 0; mi < 2; mi++) {
        int row0 = bm * 64 + warpm * 32 + mi * 16 + r;
#pragma unroll
        for (int ni = 0; ni < 6; ni++) {
            int col = warpn * 48 + ni * 8 + q2;
            float b0 = bias[col], b1 = bias[col + 1];
            size_t o0 = (size_t)row0 * N + col, o1 = (size_t)(row0 + 8) * N + col;
            out[o0]     += acc[mi][ni][0] + b0;
            out[o0 + 1] += acc[mi][ni][1] + b1;
            out[o1]     += acc[mi][ni][2] + b0;
            out[o1 + 1] += acc[mi][ni][3] + b1;
        }
    }
}

// ---------------- launch ----------------
extern "C" void kernel_launch(void* const* d_in, const int* in_sizes, int n_in,
                              void* d_out, int out_size)
{
    (void)in_sizes; (void)n_in; (void)out_size;
    const float* x    = (const float*)d_in[0];
    const float* x1   = (const float*)d_in[1];
    const float* n1g  = (const float*)d_in[3];
    const float* n1b  = (const float*)d_in[4];
    const float* qw   = (const float*)d_in[5];
    const float* qb   = (const float*)d_in[6];
    const float* kvw  = (const float*)d_in[7];
    const float* kvb  = (const float*)d_in[8];
    const float* rpb  = (const float*)d_in[9];
    const float* pw   = (const float*)d_in[10];
    const float* pb   = (const float*)d_in[11];
    const float* n2g  = (const float*)d_in[12];
    const float* n2b  = (const float*)d_in[13];
    const float* f1w  = (const float*)d_in[14];
    const float* f1b  = (const float*)d_in[15];
    const float* f2w  = (const float*)d_in[16];
    const float* f2b  = (const float*)d_in[17];
    float* out = (float*)d_out;

    bf16 *xw, *x1w, *q, *kv, *ao, *h;
    cudaGetSymbolAddress((void**)&xw,  g_xw);
    cudaGetSymbolAddress((void**)&x1w, g_x1w);
    cudaGetSymbolAddress((void**)&q,   g_q);
    cudaGetSymbolAddress((void**)&kv,  g_kv);
    cudaGetSymbolAddress((void**)&ao,  g_ao);
    cudaGetSymbolAddress((void**)&h,   g_h);
    bf16 *qwb, *kvwb, *pwb, *f1wb, *f2wb;
    cudaGetSymbolAddress((void**)&qwb,  g_qwb);
    cudaGetSymbolAddress((void**)&kvwb, g_kvwb);
    cudaGetSymbolAddress((void**)&pwb,  g_pwb);
    cudaGetSymbolAddress((void**)&f1wb, g_f1wb);
    cudaGetSymbolAddress((void**)&f2wb, g_f2wb);

    cudaFuncSetAttribute(gemm192_kernel<0, false>, cudaFuncAttributeMaxDynamicSharedMemorySize, GSM_BYTES);
    cudaFuncSetAttribute(gemm192_kernel<2, false>, cudaFuncAttributeMaxDynamicSharedMemorySize, GSM_BYTES);
    cudaFuncSetAttribute(gemm192_kernel<1, true>,  cudaFuncAttributeMaxDynamicSharedMemorySize, GSM_BYTES);
    cudaFuncSetAttribute(gemm_fc2_kernel,          cudaFuncAttributeMaxDynamicSharedMemorySize, F2SM_BYTES);

    cvt_all_kernel<<<(W5 + 255) / 256, 256>>>(qw, kvw, pw, f1w, f2w);
    ln1_gather_kernel<<<MTOK / 8, 256>>>(x, x1, n1g, n1b);
    gemm192_kernel<0, false><<<MTOK / 64, 256, GSM_BYTES>>>(xw,  kvwb, kvb, kv, nullptr, nullptr, nullptr, 384);
    gemm192_kernel<0, false><<<MTOK / 64, 256, GSM_BYTES>>>(x1w, qwb,  qb,  q,  nullptr, nullptr, nullptr, 192);
    attn_kernel<<<BW * HEADS, 128>>>(rpb);
    gemm192_kernel<2, false><<<MTOK / 64, 256, GSM_BYTES>>>(ao, pwb, pb, out, x, nullptr, nullptr, 192);
    gemm192_kernel<1, true ><<<MTOK / 64, 256, GSM_BYTES>>>(out, f1wb, f1b, h, nullptr, n2g, n2b, 768);
    gemm_fc2_kernel<<<MTOK / 64, 256, F2SM_BYTES>>>(h, f2wb, f2b, out);
}